// round 15
// baseline (speedup 1.0000x reference)
#include <cuda_runtime.h>
#include <math.h>

#define BB 16      // batch
#define TT 1024    // sequence
#define JJ 128     // input dim
#define HH 64      // hidden (complex) dim

// Scratch: Bx in [b][h][t] layout (contiguous t rows for the scan).
__device__ float g_Bxt[BB * HH * TT];   // 4 MB static scratch

// ---------------------------------------------------------------------------
// tf32 helpers
// ---------------------------------------------------------------------------
__device__ __forceinline__ unsigned tf32bits(float v) {
    unsigned r;
    asm("cvt.rna.tf32.f32 %0, %1;" : "=r"(r) : "f"(v));
    return r;
}
__device__ __forceinline__ void mma_tf32(float& d0, float& d1, float& d2, float& d3,
                                         unsigned a0, unsigned a1, unsigned a2, unsigned a3,
                                         unsigned b0, unsigned b1) {
    asm("mma.sync.aligned.m16n8k8.row.col.f32.tf32.tf32.f32 "
        "{%0,%1,%2,%3}, {%4,%5,%6,%7}, {%8,%9}, {%0,%1,%2,%3};"
        : "+f"(d0), "+f"(d1), "+f"(d2), "+f"(d3)
        : "r"(a0), "r"(a1), "r"(a2), "r"(a3), "r"(b0), "r"(b1));
}
__device__ __forceinline__ unsigned fbits(float v) { return __float_as_uint(v); }

// ---------------------------------------------------------------------------
// Kernel 1: Bxt[b][h][t] = sum_j B[h][j] * x[b][t][j]   (3xTF32 tensor-core)
// ROUND-4 VERSION VERBATIM (validated 17.1us total).
// ---------------------------------------------------------------------------
#define KST 68
#define GEMM_SMEM_BYTES (4 * 64 * KST * 4)   // 69632 B

__global__ __launch_bounds__(128) void gemm_kernel(const float* __restrict__ x,
                                                   const float* __restrict__ Bm) {
    extern __shared__ __align__(16) float sm[];
    float* xhi = sm;                  // [t 0..63][j 0..63] stride 68
    float* xlo = sm + 64 * KST;
    float* bhi = sm + 2 * 64 * KST;   // [h 0..63][j 0..63] stride 68
    float* blo = sm + 3 * 64 * KST;

    const int tid  = threadIdx.x;
    const int lane = tid & 31;
    const int wid  = tid >> 5;
    const int wt   = wid >> 1;        // 0..1 -> t offset 32*wt
    const int wh   = wid & 1;         // 0..1 -> h offset 32*wh
    const int b    = blockIdx.x >> 4;
    const int t0   = (blockIdx.x & 15) * 64;

    const int lr = lane >> 2;         // 0..7
    const int lc = lane & 3;          // 0..3

    float acc[2][4][4];
#pragma unroll
    for (int m = 0; m < 2; ++m)
#pragma unroll
        for (int n = 0; n < 4; ++n)
#pragma unroll
            for (int q = 0; q < 4; ++q) acc[m][n][q] = 0.f;

    const float4* x4 = reinterpret_cast<const float4*>(x);
    const float4* B4 = reinterpret_cast<const float4*>(Bm);

    for (int kc = 0; kc < 2; ++kc) {
        if (kc) __syncthreads();
        // Stage x chunk: 64 t x 16 float4, split hi/lo
#pragma unroll
        for (int i = 0; i < 8; ++i) {
            int f  = tid + 128 * i;
            int t  = f >> 4;
            int jq = f & 15;
            float4 v = x4[(b * TT + t0 + t) * 32 + kc * 16 + jq];
            float4 hv, lv;
            hv.x = __uint_as_float(tf32bits(v.x)); lv.x = v.x - hv.x;
            hv.y = __uint_as_float(tf32bits(v.y)); lv.y = v.y - hv.y;
            hv.z = __uint_as_float(tf32bits(v.z)); lv.z = v.z - hv.z;
            hv.w = __uint_as_float(tf32bits(v.w)); lv.w = v.w - hv.w;
            *reinterpret_cast<float4*>(&xhi[t * KST + jq * 4]) = hv;
            *reinterpret_cast<float4*>(&xlo[t * KST + jq * 4]) = lv;
        }
        // Stage B chunk: 64 h x 16 float4, split hi/lo
#pragma unroll
        for (int i = 0; i < 8; ++i) {
            int f  = tid + 128 * i;
            int h  = f >> 4;
            int jq = f & 15;
            float4 v = B4[h * 32 + kc * 16 + jq];
            float4 hv, lv;
            hv.x = __uint_as_float(tf32bits(v.x)); lv.x = v.x - hv.x;
            hv.y = __uint_as_float(tf32bits(v.y)); lv.y = v.y - hv.y;
            hv.z = __uint_as_float(tf32bits(v.z)); lv.z = v.z - hv.z;
            hv.w = __uint_as_float(tf32bits(v.w)); lv.w = v.w - hv.w;
            *reinterpret_cast<float4*>(&bhi[h * KST + jq * 4]) = hv;
            *reinterpret_cast<float4*>(&blo[h * KST + jq * 4]) = lv;
        }
        __syncthreads();

#pragma unroll
        for (int ks = 0; ks < 8; ++ks) {
            const int j0 = ks * 8;
            unsigned ah[2][4], al[2][4];
#pragma unroll
            for (int m = 0; m < 2; ++m) {
                int base = (wt * 32 + m * 16 + lr) * KST + j0 + lc;
                ah[m][0] = fbits(xhi[base]);
                ah[m][1] = fbits(xhi[base + 8 * KST]);
                ah[m][2] = fbits(xhi[base + 4]);
                ah[m][3] = fbits(xhi[base + 8 * KST + 4]);
                al[m][0] = fbits(xlo[base]);
                al[m][1] = fbits(xlo[base + 8 * KST]);
                al[m][2] = fbits(xlo[base + 4]);
                al[m][3] = fbits(xlo[base + 8 * KST + 4]);
            }
#pragma unroll
            for (int n = 0; n < 4; ++n) {
                int hb = (wh * 32 + n * 8 + lr) * KST + j0 + lc;
                unsigned bh0 = fbits(bhi[hb]);
                unsigned bh1 = fbits(bhi[hb + 4]);
                unsigned bl0 = fbits(blo[hb]);
                unsigned bl1 = fbits(blo[hb + 4]);
#pragma unroll
                for (int m = 0; m < 2; ++m) {
                    mma_tf32(acc[m][n][0], acc[m][n][1], acc[m][n][2], acc[m][n][3],
                             ah[m][0], ah[m][1], ah[m][2], ah[m][3], bh0, bh1);
                    mma_tf32(acc[m][n][0], acc[m][n][1], acc[m][n][2], acc[m][n][3],
                             ah[m][0], ah[m][1], ah[m][2], ah[m][3], bl0, bl1);
                    mma_tf32(acc[m][n][0], acc[m][n][1], acc[m][n][2], acc[m][n][3],
                             al[m][0], al[m][1], al[m][2], al[m][3], bh0, bh1);
                }
            }
        }
    }
    __syncthreads();

    // Epilogue: stage D into smem as [h][t] (stride 68), then coalesced
    // float4 writes of g_Bxt[b][h][t] rows.
    float* sD = sm;   // 64 * 68 floats, aliases xhi (safe after sync)
#pragma unroll
    for (int m = 0; m < 2; ++m)
#pragma unroll
        for (int n = 0; n < 4; ++n) {
            int tr = wt * 32 + m * 16 + lr;
            int hc = wh * 32 + n * 8 + 2 * lc;
            sD[hc * KST + tr]            = acc[m][n][0];
            sD[(hc + 1) * KST + tr]      = acc[m][n][1];
            sD[hc * KST + tr + 8]        = acc[m][n][2];
            sD[(hc + 1) * KST + tr + 8]  = acc[m][n][3];
        }
    __syncthreads();
    {
        int h  = tid >> 1;
        int tq = tid & 1;
        float* dst = &g_Bxt[(b * HH + h) * TT + t0 + tq * 32];
        const float* srcp = &sD[h * KST + tq * 32];
#pragma unroll
        for (int i = 0; i < 8; ++i) {
            *reinterpret_cast<float4*>(dst + i * 4) =
                *reinterpret_cast<const float4*>(srcp + i * 4);
        }
    }
}

// ---------------------------------------------------------------------------
// Kernel 2: complex linear scan  y_t = lam*y_{t-1} + Bx_t,  y_{-1} = 1.
// CHUNK = 8 (was 16): 131072 threads -> ~28 warps/SM; chain 72 cyc/phase.
// Block (b, 4 h) x 512 thr: tg = tid>>2 (128 chunks of 8 t), hl = tid&3.
// Carry combine per h: 4 warps x KS-32 (ratio P = lam^8) + 4-quarter bridge
// (ratio Q32 = lam^256, <=3-step Horner) — round-2 algebra, one more level.
// ---------------------------------------------------------------------------
#define CST 5   // carry row stride (4 h + pad, odd -> conflict-free phase B)

__global__ __launch_bounds__(512) void scan_kernel(const float* __restrict__ nu,
                                                   const float* __restrict__ theta,
                                                   float* __restrict__ out) {
    __shared__ float svr[128 * CST];
    __shared__ float svi[128 * CST];
    __shared__ float qtr[4 * 4], qti[4 * 4];   // [hw][quarter] inclusive totals

    const int tid = threadIdx.x;
    const int tg  = tid >> 2;          // 0..127  t-chunk (8 steps)
    const int hl  = tid & 3;           // 0..3
    const int b   = blockIdx.y;
    const int hb  = blockIdx.x * 4;
    const int h   = hb + hl;

    const float mag = expf(-expf(nu[h]));
    float sn0, cs0;
    sincosf(theta[h], &sn0, &cs0);
    const float lr = mag * cs0;
    const float li = mag * sn0;

    // Load 8 inputs (2 x LDG.128)
    float u[8];
    const float4* src =
        reinterpret_cast<const float4*>(&g_Bxt[(b * HH + h) * TT + tg * 8]);
    {
        float4 v0 = src[0];
        float4 v1 = src[1];
        u[0] = v0.x; u[1] = v0.y; u[2] = v0.z; u[3] = v0.w;
        u[4] = v1.x; u[5] = v1.y; u[6] = v1.z; u[7] = v1.w;
    }

    // Phase A: local scan from zero -> chunk value V
    float yr = 0.f, yi = 0.f;
#pragma unroll
    for (int k = 0; k < 8; ++k) {
        float nyr = fmaf(lr, yr, fmaf(-li, yi, u[k]));
        float nyi = fmaf(lr, yi, li * yr);
        yr = nyr; yi = nyi;
    }
    svr[tg * CST + hl] = yr;
    svi[tg * CST + hl] = yi;
    __syncthreads();

    // Phase B: warp (hw, q) scans chunks q*32 + lane of h = hb + hw.
    const int lane = tid & 31;
    const int wid  = tid >> 5;          // 0..15
    const int hw   = wid & 3;
    const int q    = wid >> 2;          // quarter 0..3
    const int c    = q * 32 + lane;

    const int   h2   = hb + hw;
    const float mag2 = expf(-expf(nu[h2]));
    float sn2, cs2;
    sincosf(theta[h2], &sn2, &cs2);
    float ar = mag2 * cs2;
    float ai = mag2 * sn2;

    // P = lam^8 via 3 squarings
    float pr = ar, pi = ai;
#pragma unroll
    for (int s = 0; s < 3; ++s) {
        float nr = pr * pr - pi * pi;
        float ni = 2.f * pr * pi;
        pr = nr; pi = ni;
    }
    // P^(2^d), d = 0..4
    float Pr[5], Pi[5];
    Pr[0] = pr; Pi[0] = pi;
#pragma unroll
    for (int d = 1; d < 5; ++d) {
        Pr[d] = Pr[d - 1] * Pr[d - 1] - Pi[d - 1] * Pi[d - 1];
        Pi[d] = 2.f * Pr[d - 1] * Pi[d - 1];
    }
    // Q32 = P^32 = lam^256
    const float Q32r = Pr[4] * Pr[4] - Pi[4] * Pi[4];
    const float Q32i = 2.f * Pr[4] * Pi[4];

    float Vr = svr[c * CST + hw];
    float Vi = svi[c * CST + hw];
    // Kogge-Stone inclusive scan within quarter: V_i += P^(2^d) * V_{i-2^d}
#pragma unroll
    for (int d = 0; d < 5; ++d) {
        int sh = 1 << d;
        float orr = __shfl_up_sync(0xffffffffu, Vr, sh);
        float oii = __shfl_up_sync(0xffffffffu, Vi, sh);
        if (lane >= sh) {
            float nVr = Vr + (Pr[d] * orr - Pi[d] * oii);
            float nVi = Vi + (Pr[d] * oii + Pi[d] * orr);
            Vr = nVr; Vi = nVi;
        }
    }
    // Publish quarter inclusive totals
    if (lane == 31) { qtr[hw * 4 + q] = Vr; qti[hw * 4 + q] = Vi; }
    __syncthreads();

    // Base_q = E at end of quarter q-1 (incl. initial state y_{-1}=1):
    // Base = 1; for g in 0..q-1: Base = Q32*Base + T_g   (<=3 steps)
    float Br_ = 1.f, Bi_ = 0.f;
#pragma unroll
    for (int g = 0; g < 3; ++g) {
        if (g < q) {
            float nr = Q32r * Br_ - Q32i * Bi_ + qtr[hw * 4 + g];
            float ni = Q32r * Bi_ + Q32i * Br_ + qti[hw * 4 + g];
            Br_ = nr; Bi_ = ni;
        }
    }
    // Exclusive local prefix
    float Wr = __shfl_up_sync(0xffffffffu, Vr, 1);
    float Wi = __shfl_up_sync(0xffffffffu, Vi, 1);
    if (lane == 0) { Wr = 0.f; Wi = 0.f; }
    // P^lane
    float qr = 1.f, qi = 0.f;
#pragma unroll
    for (int d = 0; d < 5; ++d) {
        if ((lane >> d) & 1) {
            float nr = qr * Pr[d] - qi * Pi[d];
            float ni = qr * Pi[d] + qi * Pr[d];
            qr = nr; qi = ni;
        }
    }
    // Incoming state for chunk c: S = W + P^lane * Base
    svr[c * CST + hw] = Wr + (qr * Br_ - qi * Bi_);
    svi[c * CST + hw] = Wi + (qr * Bi_ + qi * Br_);
    __syncthreads();

    // Phase C: re-run chunk with true incoming state.
    yr = svr[tg * CST + hl];
    yi = svi[tg * CST + hl];
    float* op = out + (b * TT + tg * 8) * (2 * HH) + h;
#pragma unroll
    for (int k = 0; k < 8; ++k) {
        float nyr = fmaf(lr, yr, fmaf(-li, yi, u[k]));
        float nyi = fmaf(lr, yi, li * yr);
        yr = nyr; yi = nyi;
        op[k * 128]      = yr;   // re at [b,t,h]
        op[k * 128 + 64] = yi;   // im at [b,t,H+h]
    }
}

// ---------------------------------------------------------------------------
extern "C" void kernel_launch(void* const* d_in, const int* in_sizes, int n_in,
                              void* d_out, int out_size) {
    const float* x     = (const float*)d_in[0];   // [16,1024,128]
    const float* Bm    = (const float*)d_in[1];   // [64,128]
    const float* nu    = (const float*)d_in[2];   // [64]
    const float* theta = (const float*)d_in[3];   // [64]
    float* out = (float*)d_out;                   // [16,1024,128]

    cudaFuncSetAttribute(gemm_kernel,
                         cudaFuncAttributeMaxDynamicSharedMemorySize,
                         GEMM_SMEM_BYTES);
    gemm_kernel<<<256, 128, GEMM_SMEM_BYTES>>>(x, Bm);
    scan_kernel<<<dim3(16, 16), 512>>>(nu, theta, out);
}

// round 16
// speedup vs baseline: 1.0017x; 1.0017x over previous
#include <cuda_runtime.h>
#include <math.h>

#define BB 16      // batch
#define TT 1024    // sequence
#define JJ 128     // input dim
#define HH 64      // hidden (complex) dim

// Scratch: Bx in [b][h][t] layout (contiguous t rows for the scan).
__device__ float g_Bxt[BB * HH * TT];   // 4 MB static scratch
// lam per h, computed ONCE (64 values) — removes all MUFU from the scan.
__device__ __align__(8) float2 g_lam[HH];

// ---------------------------------------------------------------------------
// tf32 helpers
// ---------------------------------------------------------------------------
__device__ __forceinline__ unsigned tf32bits(float v) {
    unsigned r;
    asm("cvt.rna.tf32.f32 %0, %1;" : "=r"(r) : "f"(v));
    return r;
}
__device__ __forceinline__ void mma_tf32(float& d0, float& d1, float& d2, float& d3,
                                         unsigned a0, unsigned a1, unsigned a2, unsigned a3,
                                         unsigned b0, unsigned b1) {
    asm("mma.sync.aligned.m16n8k8.row.col.f32.tf32.tf32.f32 "
        "{%0,%1,%2,%3}, {%4,%5,%6,%7}, {%8,%9}, {%0,%1,%2,%3};"
        : "+f"(d0), "+f"(d1), "+f"(d2), "+f"(d3)
        : "r"(a0), "r"(a1), "r"(a2), "r"(a3), "r"(b0), "r"(b1));
}
__device__ __forceinline__ unsigned fbits(float v) { return __float_as_uint(v); }

// ---------------------------------------------------------------------------
// lam_kernel: compute lam_h = exp(-exp(nu)) * (cos th, sin th) ONCE per h.
// ---------------------------------------------------------------------------
__global__ void lam_kernel(const float* __restrict__ nu,
                           const float* __restrict__ theta) {
    int h = threadIdx.x;
    float m = expf(-expf(nu[h]));
    float s, c;
    sincosf(theta[h], &s, &c);
    g_lam[h] = make_float2(m * c, m * s);
}

// ---------------------------------------------------------------------------
// Kernel 1: Bxt[b][h][t] = sum_j B[h][j] * x[b][t][j]   (3xTF32 tensor-core)
// ROUND-4 VERSION VERBATIM (validated 17.1us total).
// ---------------------------------------------------------------------------
#define KST 68
#define GEMM_SMEM_BYTES (4 * 64 * KST * 4)   // 69632 B

__global__ __launch_bounds__(128) void gemm_kernel(const float* __restrict__ x,
                                                   const float* __restrict__ Bm) {
    extern __shared__ __align__(16) float sm[];
    float* xhi = sm;                  // [t 0..63][j 0..63] stride 68
    float* xlo = sm + 64 * KST;
    float* bhi = sm + 2 * 64 * KST;   // [h 0..63][j 0..63] stride 68
    float* blo = sm + 3 * 64 * KST;

    const int tid  = threadIdx.x;
    const int lane = tid & 31;
    const int wid  = tid >> 5;
    const int wt   = wid >> 1;        // 0..1 -> t offset 32*wt
    const int wh   = wid & 1;         // 0..1 -> h offset 32*wh
    const int b    = blockIdx.x >> 4;
    const int t0   = (blockIdx.x & 15) * 64;

    const int lr = lane >> 2;         // 0..7
    const int lc = lane & 3;          // 0..3

    float acc[2][4][4];
#pragma unroll
    for (int m = 0; m < 2; ++m)
#pragma unroll
        for (int n = 0; n < 4; ++n)
#pragma unroll
            for (int q = 0; q < 4; ++q) acc[m][n][q] = 0.f;

    const float4* x4 = reinterpret_cast<const float4*>(x);
    const float4* B4 = reinterpret_cast<const float4*>(Bm);

    for (int kc = 0; kc < 2; ++kc) {
        if (kc) __syncthreads();
        // Stage x chunk: 64 t x 16 float4, split hi/lo
#pragma unroll
        for (int i = 0; i < 8; ++i) {
            int f  = tid + 128 * i;
            int t  = f >> 4;
            int jq = f & 15;
            float4 v = x4[(b * TT + t0 + t) * 32 + kc * 16 + jq];
            float4 hv, lv;
            hv.x = __uint_as_float(tf32bits(v.x)); lv.x = v.x - hv.x;
            hv.y = __uint_as_float(tf32bits(v.y)); lv.y = v.y - hv.y;
            hv.z = __uint_as_float(tf32bits(v.z)); lv.z = v.z - hv.z;
            hv.w = __uint_as_float(tf32bits(v.w)); lv.w = v.w - hv.w;
            *reinterpret_cast<float4*>(&xhi[t * KST + jq * 4]) = hv;
            *reinterpret_cast<float4*>(&xlo[t * KST + jq * 4]) = lv;
        }
        // Stage B chunk: 64 h x 16 float4, split hi/lo
#pragma unroll
        for (int i = 0; i < 8; ++i) {
            int f  = tid + 128 * i;
            int h  = f >> 4;
            int jq = f & 15;
            float4 v = B4[h * 32 + kc * 16 + jq];
            float4 hv, lv;
            hv.x = __uint_as_float(tf32bits(v.x)); lv.x = v.x - hv.x;
            hv.y = __uint_as_float(tf32bits(v.y)); lv.y = v.y - hv.y;
            hv.z = __uint_as_float(tf32bits(v.z)); lv.z = v.z - hv.z;
            hv.w = __uint_as_float(tf32bits(v.w)); lv.w = v.w - hv.w;
            *reinterpret_cast<float4*>(&bhi[h * KST + jq * 4]) = hv;
            *reinterpret_cast<float4*>(&blo[h * KST + jq * 4]) = lv;
        }
        __syncthreads();

#pragma unroll
        for (int ks = 0; ks < 8; ++ks) {
            const int j0 = ks * 8;
            unsigned ah[2][4], al[2][4];
#pragma unroll
            for (int m = 0; m < 2; ++m) {
                int base = (wt * 32 + m * 16 + lr) * KST + j0 + lc;
                ah[m][0] = fbits(xhi[base]);
                ah[m][1] = fbits(xhi[base + 8 * KST]);
                ah[m][2] = fbits(xhi[base + 4]);
                ah[m][3] = fbits(xhi[base + 8 * KST + 4]);
                al[m][0] = fbits(xlo[base]);
                al[m][1] = fbits(xlo[base + 8 * KST]);
                al[m][2] = fbits(xlo[base + 4]);
                al[m][3] = fbits(xlo[base + 8 * KST + 4]);
            }
#pragma unroll
            for (int n = 0; n < 4; ++n) {
                int hb = (wh * 32 + n * 8 + lr) * KST + j0 + lc;
                unsigned bh0 = fbits(bhi[hb]);
                unsigned bh1 = fbits(bhi[hb + 4]);
                unsigned bl0 = fbits(blo[hb]);
                unsigned bl1 = fbits(blo[hb + 4]);
#pragma unroll
                for (int m = 0; m < 2; ++m) {
                    mma_tf32(acc[m][n][0], acc[m][n][1], acc[m][n][2], acc[m][n][3],
                             ah[m][0], ah[m][1], ah[m][2], ah[m][3], bh0, bh1);
                    mma_tf32(acc[m][n][0], acc[m][n][1], acc[m][n][2], acc[m][n][3],
                             ah[m][0], ah[m][1], ah[m][2], ah[m][3], bl0, bl1);
                    mma_tf32(acc[m][n][0], acc[m][n][1], acc[m][n][2], acc[m][n][3],
                             al[m][0], al[m][1], al[m][2], al[m][3], bh0, bh1);
                }
            }
        }
    }
    __syncthreads();

    // Epilogue: stage D into smem as [h][t] (stride 68), then coalesced
    // float4 writes of g_Bxt[b][h][t] rows.
    float* sD = sm;   // 64 * 68 floats, aliases xhi (safe after sync)
#pragma unroll
    for (int m = 0; m < 2; ++m)
#pragma unroll
        for (int n = 0; n < 4; ++n) {
            int tr = wt * 32 + m * 16 + lr;
            int hc = wh * 32 + n * 8 + 2 * lc;
            sD[hc * KST + tr]            = acc[m][n][0];
            sD[(hc + 1) * KST + tr]      = acc[m][n][1];
            sD[hc * KST + tr + 8]        = acc[m][n][2];
            sD[(hc + 1) * KST + tr + 8]  = acc[m][n][3];
        }
    __syncthreads();
    {
        int h  = tid >> 1;
        int tq = tid & 1;
        float* dst = &g_Bxt[(b * HH + h) * TT + t0 + tq * 32];
        const float* srcp = &sD[h * KST + tq * 32];
#pragma unroll
        for (int i = 0; i < 8; ++i) {
            *reinterpret_cast<float4*>(dst + i * 4) =
                *reinterpret_cast<const float4*>(srcp + i * 4);
        }
    }
}

// ---------------------------------------------------------------------------
// Kernel 2: complex linear scan  y_t = lam*y_{t-1} + Bx_t,  y_{-1} = 1.
// Round-15 structure (chunk 8, 512 thr, 4-quarter bridge) with ZERO MUFU:
// lam comes from g_lam (one float2 broadcast load); all powers are FMA
// squarings.
// ---------------------------------------------------------------------------
#define CST 5   // carry row stride (4 h + pad, odd -> conflict-free phase B)

__global__ __launch_bounds__(512) void scan_kernel(float* __restrict__ out) {
    __shared__ float svr[128 * CST];
    __shared__ float svi[128 * CST];
    __shared__ float qtr[4 * 4], qti[4 * 4];   // [hw][quarter] inclusive totals

    const int tid = threadIdx.x;
    const int tg  = tid >> 2;          // 0..127  t-chunk (8 steps)
    const int hl  = tid & 3;           // 0..3
    const int b   = blockIdx.y;
    const int hb  = blockIdx.x * 4;
    const int h   = hb + hl;

    const float2 L = g_lam[h];
    const float lr = L.x;
    const float li = L.y;

    // Load 8 inputs (2 x LDG.128)
    float u[8];
    const float4* src =
        reinterpret_cast<const float4*>(&g_Bxt[(b * HH + h) * TT + tg * 8]);
    {
        float4 v0 = src[0];
        float4 v1 = src[1];
        u[0] = v0.x; u[1] = v0.y; u[2] = v0.z; u[3] = v0.w;
        u[4] = v1.x; u[5] = v1.y; u[6] = v1.z; u[7] = v1.w;
    }

    // Phase A: local scan from zero -> chunk value V
    float yr = 0.f, yi = 0.f;
#pragma unroll
    for (int k = 0; k < 8; ++k) {
        float nyr = fmaf(lr, yr, fmaf(-li, yi, u[k]));
        float nyi = fmaf(lr, yi, li * yr);
        yr = nyr; yi = nyi;
    }
    svr[tg * CST + hl] = yr;
    svi[tg * CST + hl] = yi;
    __syncthreads();

    // Phase B: warp (hw, q) scans chunks q*32 + lane of h = hb + hw.
    const int lane = tid & 31;
    const int wid  = tid >> 5;          // 0..15
    const int hw   = wid & 3;
    const int q    = wid >> 2;          // quarter 0..3
    const int c    = q * 32 + lane;

    const float2 L2 = g_lam[hb + hw];
    float ar = L2.x;
    float ai = L2.y;

    // P = lam^8 via 3 squarings (FMA only)
    float pr = ar, pi = ai;
#pragma unroll
    for (int s = 0; s < 3; ++s) {
        float nr = pr * pr - pi * pi;
        float ni = 2.f * pr * pi;
        pr = nr; pi = ni;
    }
    // P^(2^d), d = 0..4
    float Pr[5], Pi[5];
    Pr[0] = pr; Pi[0] = pi;
#pragma unroll
    for (int d = 1; d < 5; ++d) {
        Pr[d] = Pr[d - 1] * Pr[d - 1] - Pi[d - 1] * Pi[d - 1];
        Pi[d] = 2.f * Pr[d - 1] * Pi[d - 1];
    }
    // Q32 = P^32 = lam^256
    const float Q32r = Pr[4] * Pr[4] - Pi[4] * Pi[4];
    const float Q32i = 2.f * Pr[4] * Pi[4];

    float Vr = svr[c * CST + hw];
    float Vi = svi[c * CST + hw];
    // Kogge-Stone inclusive scan within quarter: V_i += P^(2^d) * V_{i-2^d}
#pragma unroll
    for (int d = 0; d < 5; ++d) {
        int sh = 1 << d;
        float orr = __shfl_up_sync(0xffffffffu, Vr, sh);
        float oii = __shfl_up_sync(0xffffffffu, Vi, sh);
        if (lane >= sh) {
            float nVr = Vr + (Pr[d] * orr - Pi[d] * oii);
            float nVi = Vi + (Pr[d] * oii + Pi[d] * orr);
            Vr = nVr; Vi = nVi;
        }
    }
    // Publish quarter inclusive totals
    if (lane == 31) { qtr[hw * 4 + q] = Vr; qti[hw * 4 + q] = Vi; }
    __syncthreads();

    // Base_q = E at end of quarter q-1 (incl. initial state y_{-1}=1):
    // Base = 1; for g in 0..q-1: Base = Q32*Base + T_g   (<=3 steps)
    float Br_ = 1.f, Bi_ = 0.f;
#pragma unroll
    for (int g = 0; g < 3; ++g) {
        if (g < q) {
            float nr = Q32r * Br_ - Q32i * Bi_ + qtr[hw * 4 + g];
            float ni = Q32r * Bi_ + Q32i * Br_ + qti[hw * 4 + g];
            Br_ = nr; Bi_ = ni;
        }
    }
    // Exclusive local prefix
    float Wr = __shfl_up_sync(0xffffffffu, Vr, 1);
    float Wi = __shfl_up_sync(0xffffffffu, Vi, 1);
    if (lane == 0) { Wr = 0.f; Wi = 0.f; }
    // P^lane
    float qr = 1.f, qi = 0.f;
#pragma unroll
    for (int d = 0; d < 5; ++d) {
        if ((lane >> d) & 1) {
            float nr = qr * Pr[d] - qi * Pi[d];
            float ni = qr * Pi[d] + qi * Pr[d];
            qr = nr; qi = ni;
        }
    }
    // Incoming state for chunk c: S = W + P^lane * Base
    svr[c * CST + hw] = Wr + (qr * Br_ - qi * Bi_);
    svi[c * CST + hw] = Wi + (qr * Bi_ + qi * Br_);
    __syncthreads();

    // Phase C: re-run chunk with true incoming state.
    yr = svr[tg * CST + hl];
    yi = svi[tg * CST + hl];
    float* op = out + (b * TT + tg * 8) * (2 * HH) + h;
#pragma unroll
    for (int k = 0; k < 8; ++k) {
        float nyr = fmaf(lr, yr, fmaf(-li, yi, u[k]));
        float nyi = fmaf(lr, yi, li * yr);
        yr = nyr; yi = nyi;
        op[k * 128]      = yr;   // re at [b,t,h]
        op[k * 128 + 64] = yi;   // im at [b,t,H+h]
    }
}

// ---------------------------------------------------------------------------
extern "C" void kernel_launch(void* const* d_in, const int* in_sizes, int n_in,
                              void* d_out, int out_size) {
    const float* x     = (const float*)d_in[0];   // [16,1024,128]
    const float* Bm    = (const float*)d_in[1];   // [64,128]
    const float* nu    = (const float*)d_in[2];   // [64]
    const float* theta = (const float*)d_in[3];   // [64]
    float* out = (float*)d_out;                   // [16,1024,128]

    cudaFuncSetAttribute(gemm_kernel,
                         cudaFuncAttributeMaxDynamicSharedMemorySize,
                         GEMM_SMEM_BYTES);
    lam_kernel<<<1, 64>>>(nu, theta);
    gemm_kernel<<<256, 128, GEMM_SMEM_BYTES>>>(x, Bm);
    scan_kernel<<<dim3(16, 16), 512>>>(out);
}

// round 17
// speedup vs baseline: 1.1215x; 1.1196x over previous
#include <cuda_runtime.h>
#include <math.h>

#define BB 16      // batch
#define TT 1024    // sequence
#define JJ 128     // input dim
#define HH 64      // hidden (complex) dim

// Scratch: Bx in [b][h][t] layout (contiguous t rows for the scan).
__device__ float g_Bxt[BB * HH * TT];   // 4 MB static scratch

// ---------------------------------------------------------------------------
// tf32 helpers
// ---------------------------------------------------------------------------
__device__ __forceinline__ unsigned tf32bits(float v) {
    unsigned r;
    asm("cvt.rna.tf32.f32 %0, %1;" : "=r"(r) : "f"(v));
    return r;
}
__device__ __forceinline__ void mma_tf32(float& d0, float& d1, float& d2, float& d3,
                                         unsigned a0, unsigned a1, unsigned a2, unsigned a3,
                                         unsigned b0, unsigned b1) {
    asm("mma.sync.aligned.m16n8k8.row.col.f32.tf32.tf32.f32 "
        "{%0,%1,%2,%3}, {%4,%5,%6,%7}, {%8,%9}, {%0,%1,%2,%3};"
        : "+f"(d0), "+f"(d1), "+f"(d2), "+f"(d3)
        : "r"(a0), "r"(a1), "r"(a2), "r"(a3), "r"(b0), "r"(b1));
}
__device__ __forceinline__ unsigned fbits(float v) { return __float_as_uint(v); }

// ---------------------------------------------------------------------------
// Kernel 1: Bxt[b][h][t] = sum_j B[h][j] * x[b][t][j]   (SINGLE-TF32 MMA)
// Round-4 structure, hi/lo split removed: 1/3 the MMAs, half the smem/LDS.
// Grid 256 = 16 b x 16 t-segs of 64. Block 128 thr = 4 warps in 2x2 (t,h);
// warp tile 32t x 32h. K=128 in 2 chunks of 64 staged as tf32.
// ---------------------------------------------------------------------------
#define KST 68
#define GEMM_SMEM_BYTES (2 * 64 * KST * 4)   // 34816 B

__global__ __launch_bounds__(128) void gemm_kernel(const float* __restrict__ x,
                                                   const float* __restrict__ Bm) {
    extern __shared__ __align__(16) float sm[];
    float* xtf = sm;                  // [t 0..63][j 0..63] stride 68
    float* btf = sm + 64 * KST;       // [h 0..63][j 0..63] stride 68

    const int tid  = threadIdx.x;
    const int lane = tid & 31;
    const int wid  = tid >> 5;
    const int wt   = wid >> 1;        // 0..1 -> t offset 32*wt
    const int wh   = wid & 1;         // 0..1 -> h offset 32*wh
    const int b    = blockIdx.x >> 4;
    const int t0   = (blockIdx.x & 15) * 64;

    const int lr = lane >> 2;         // 0..7
    const int lc = lane & 3;          // 0..3

    float acc[2][4][4];
#pragma unroll
    for (int m = 0; m < 2; ++m)
#pragma unroll
        for (int n = 0; n < 4; ++n)
#pragma unroll
            for (int q = 0; q < 4; ++q) acc[m][n][q] = 0.f;

    const float4* x4 = reinterpret_cast<const float4*>(x);
    const float4* B4 = reinterpret_cast<const float4*>(Bm);

    for (int kc = 0; kc < 2; ++kc) {
        if (kc) __syncthreads();
        // Stage x chunk: 64 t x 16 float4, tf32-round
#pragma unroll
        for (int i = 0; i < 8; ++i) {
            int f  = tid + 128 * i;
            int t  = f >> 4;
            int jq = f & 15;
            float4 v = x4[(b * TT + t0 + t) * 32 + kc * 16 + jq];
            float4 hv;
            hv.x = __uint_as_float(tf32bits(v.x));
            hv.y = __uint_as_float(tf32bits(v.y));
            hv.z = __uint_as_float(tf32bits(v.z));
            hv.w = __uint_as_float(tf32bits(v.w));
            *reinterpret_cast<float4*>(&xtf[t * KST + jq * 4]) = hv;
        }
        // Stage B chunk: 64 h x 16 float4, tf32-round
#pragma unroll
        for (int i = 0; i < 8; ++i) {
            int f  = tid + 128 * i;
            int h  = f >> 4;
            int jq = f & 15;
            float4 v = B4[h * 32 + kc * 16 + jq];
            float4 hv;
            hv.x = __uint_as_float(tf32bits(v.x));
            hv.y = __uint_as_float(tf32bits(v.y));
            hv.z = __uint_as_float(tf32bits(v.z));
            hv.w = __uint_as_float(tf32bits(v.w));
            *reinterpret_cast<float4*>(&btf[h * KST + jq * 4]) = hv;
        }
        __syncthreads();

#pragma unroll
        for (int ks = 0; ks < 8; ++ks) {
            const int j0 = ks * 8;
            unsigned ah[2][4];
#pragma unroll
            for (int m = 0; m < 2; ++m) {
                int base = (wt * 32 + m * 16 + lr) * KST + j0 + lc;
                ah[m][0] = fbits(xtf[base]);
                ah[m][1] = fbits(xtf[base + 8 * KST]);
                ah[m][2] = fbits(xtf[base + 4]);
                ah[m][3] = fbits(xtf[base + 8 * KST + 4]);
            }
#pragma unroll
            for (int n = 0; n < 4; ++n) {
                int hb = (wh * 32 + n * 8 + lr) * KST + j0 + lc;
                unsigned bh0 = fbits(btf[hb]);
                unsigned bh1 = fbits(btf[hb + 4]);
#pragma unroll
                for (int m = 0; m < 2; ++m) {
                    mma_tf32(acc[m][n][0], acc[m][n][1], acc[m][n][2], acc[m][n][3],
                             ah[m][0], ah[m][1], ah[m][2], ah[m][3], bh0, bh1);
                }
            }
        }
    }
    __syncthreads();

    // Epilogue: stage D into smem as [h][t] (stride 68), then coalesced
    // float4 writes of g_Bxt[b][h][t] rows.
    float* sD = sm;   // 64 * 68 floats, aliases xtf (safe after sync)
#pragma unroll
    for (int m = 0; m < 2; ++m)
#pragma unroll
        for (int n = 0; n < 4; ++n) {
            int tr = wt * 32 + m * 16 + lr;
            int hc = wh * 32 + n * 8 + 2 * lc;
            sD[hc * KST + tr]            = acc[m][n][0];
            sD[(hc + 1) * KST + tr]      = acc[m][n][1];
            sD[hc * KST + tr + 8]        = acc[m][n][2];
            sD[(hc + 1) * KST + tr + 8]  = acc[m][n][3];
        }
    __syncthreads();
    {
        int h  = tid >> 1;
        int tq = tid & 1;
        float* dst = &g_Bxt[(b * HH + h) * TT + t0 + tq * 32];
        const float* srcp = &sD[h * KST + tq * 32];
#pragma unroll
        for (int i = 0; i < 8; ++i) {
            *reinterpret_cast<float4*>(dst + i * 4) =
                *reinterpret_cast<const float4*>(srcp + i * 4);
        }
    }
}

// ---------------------------------------------------------------------------
// Kernel 2: complex linear scan  y_t = lam*y_{t-1} + Bx_t,  y_{-1} = 1.
// ROUND-4 VERSION VERBATIM (best measured partner: 17.1us total).
// Block = (b, 8 h), 512 threads = 64 t-chunks x 8 h, chunk = 16 steps.
// ---------------------------------------------------------------------------
__global__ __launch_bounds__(512) void scan_kernel(const float* __restrict__ nu,
                                                   const float* __restrict__ theta,
                                                   float* __restrict__ out) {
    __shared__ float svr[64 * 9];
    __shared__ float svi[64 * 9];
    __shared__ float sbr[8], sbi[8];

    const int tid = threadIdx.x;
    const int tg  = tid >> 3;          // 0..63  t-chunk
    const int hl  = tid & 7;           // 0..7
    const int b   = blockIdx.y;
    const int hb  = blockIdx.x * 8;
    const int h   = hb + hl;

    const float mag = expf(-expf(nu[h]));
    const float lr  = mag * cosf(theta[h]);
    const float li  = mag * sinf(theta[h]);

    float u[16];
    const float4* src =
        reinterpret_cast<const float4*>(&g_Bxt[(b * HH + h) * TT + tg * 16]);
#pragma unroll
    for (int q = 0; q < 4; ++q) {
        float4 v = src[q];
        u[4 * q + 0] = v.x; u[4 * q + 1] = v.y;
        u[4 * q + 2] = v.z; u[4 * q + 3] = v.w;
    }

    float yr = 0.f, yi = 0.f;
#pragma unroll
    for (int k = 0; k < 16; ++k) {
        float nyr = fmaf(lr, yr, fmaf(-li, yi, u[k]));
        float nyi = fmaf(lr, yi, li * yr);
        yr = nyr; yi = nyi;
    }
    svr[tg * 9 + hl] = yr;
    svi[tg * 9 + hl] = yi;
    __syncthreads();

    const int lane = tid & 31;
    const int wid  = tid >> 5;          // 0..15
    const int hw   = wid & 7;
    const int half = wid >> 3;
    const int c    = half * 32 + lane;

    const int   h2   = hb + hw;
    const float mag2 = expf(-expf(nu[h2]));
    float ar = mag2 * cosf(theta[h2]);
    float ai = mag2 * sinf(theta[h2]);

    float pr = ar, pi = ai;
#pragma unroll
    for (int s = 0; s < 4; ++s) {
        float nr = pr * pr - pi * pi;
        float ni = 2.f * pr * pi;
        pr = nr; pi = ni;
    }
    float Pr[5], Pi[5];
    Pr[0] = pr; Pi[0] = pi;
#pragma unroll
    for (int d = 1; d < 5; ++d) {
        Pr[d] = Pr[d - 1] * Pr[d - 1] - Pi[d - 1] * Pi[d - 1];
        Pi[d] = 2.f * Pr[d - 1] * Pi[d - 1];
    }
    const float P32r = Pr[4] * Pr[4] - Pi[4] * Pi[4];
    const float P32i = 2.f * Pr[4] * Pi[4];

    float Vr = svr[c * 9 + hw];
    float Vi = svi[c * 9 + hw];
#pragma unroll
    for (int d = 0; d < 5; ++d) {
        int sh = 1 << d;
        float orr = __shfl_up_sync(0xffffffffu, Vr, sh);
        float oii = __shfl_up_sync(0xffffffffu, Vi, sh);
        if (lane >= sh) {
            float nVr = Vr + (Pr[d] * orr - Pi[d] * oii);
            float nVi = Vi + (Pr[d] * oii + Pi[d] * orr);
            Vr = nVr; Vi = nVi;
        }
    }
    if (half == 0 && lane == 31) { sbr[hw] = Vr; sbi[hw] = Vi; }
    __syncthreads();

    float Br_ = 1.f, Bi_ = 0.f;
    if (half) {
        Br_ = P32r + sbr[hw];
        Bi_ = P32i + sbi[hw];
    }
    float Wr = __shfl_up_sync(0xffffffffu, Vr, 1);
    float Wi = __shfl_up_sync(0xffffffffu, Vi, 1);
    if (lane == 0) { Wr = 0.f; Wi = 0.f; }
    float qr = 1.f, qi = 0.f;
#pragma unroll
    for (int d = 0; d < 5; ++d) {
        if ((lane >> d) & 1) {
            float nr = qr * Pr[d] - qi * Pi[d];
            float ni = qr * Pi[d] + qi * Pr[d];
            qr = nr; qi = ni;
        }
    }
    svr[c * 9 + hw] = Wr + (qr * Br_ - qi * Bi_);
    svi[c * 9 + hw] = Wi + (qr * Bi_ + qi * Br_);
    __syncthreads();

    yr = svr[tg * 9 + hl];
    yi = svi[tg * 9 + hl];
    float* op = out + (b * TT + tg * 16) * (2 * HH) + h;
#pragma unroll
    for (int k = 0; k < 16; ++k) {
        float nyr = fmaf(lr, yr, fmaf(-li, yi, u[k]));
        float nyi = fmaf(lr, yi, li * yr);
        yr = nyr; yi = nyi;
        op[k * 128]      = yr;
        op[k * 128 + 64] = yi;
    }
}

// ---------------------------------------------------------------------------
extern "C" void kernel_launch(void* const* d_in, const int* in_sizes, int n_in,
                              void* d_out, int out_size) {
    const float* x     = (const float*)d_in[0];   // [16,1024,128]
    const float* Bm    = (const float*)d_in[1];   // [64,128]
    const float* nu    = (const float*)d_in[2];   // [64]
    const float* theta = (const float*)d_in[3];   // [64]
    float* out = (float*)d_out;                   // [16,1024,128]

    cudaFuncSetAttribute(gemm_kernel,
                         cudaFuncAttributeMaxDynamicSharedMemorySize,
                         GEMM_SMEM_BYTES);
    gemm_kernel<<<256, 128, GEMM_SMEM_BYTES>>>(x, Bm);
    scan_kernel<<<dim3(8, 16), 512>>>(nu, theta, out);
}